// round 9
// baseline (speedup 1.0000x reference)
#include <cuda_runtime.h>
#include <cstdint>

#define NUM_SEGMENTS 512
#define THREADS 512
#define ROWG (THREADS / 16)   // 32 row-groups, 16 float4 lanes per 64-float row

__device__ __forceinline__ int lower_bound_i32(const int* __restrict__ b, int n, int v) {
    int lo = 0, hi = n;
    while (lo < hi) {
        int mid = (lo + hi) >> 1;
        if (b[mid] < v) lo = mid + 1; else hi = mid;
    }
    return lo;
}

__device__ __forceinline__ uint32_t smem_u32(const void* p) {
    uint32_t a;
    asm("{ .reg .u64 t; cvta.to.shared.u64 t, %1; cvt.u32.u64 %0, t; }" : "=r"(a) : "l"(p));
    return a;
}

__device__ __forceinline__ float ld_peer_f32(uint32_t local_addr, uint32_t peer_rank) {
    uint32_t ra; float v;
    asm volatile("mapa.shared::cluster.u32 %0, %1, %2;" : "=r"(ra) : "r"(local_addr), "r"(peer_rank));
    asm volatile("ld.shared::cluster.f32 %0, [%1];" : "=f"(v) : "r"(ra));
    return v;
}

#define CLUSTER_SYNC() do { \
    asm volatile("barrier.cluster.arrive.aligned;" ::: "memory"); \
    asm volatile("barrier.cluster.wait.aligned;"   ::: "memory"); \
} while (0)

extern __shared__ char smem_pad[];   // unused; 96 KB requested to cap occupancy at 2 CTA/SM

__global__ __launch_bounds__(THREADS, 2) __cluster_dims__(2, 1, 1)
void pairnorm_kernel(const float4* __restrict__ x4,
                     const int* __restrict__ batch,     // int32 (JAX x64 disabled)
                     float4* __restrict__ out4,
                     int N)
{
    __shared__ float4 s_red[ROWG * 16];        // 8 KB tree-reduce scratch
    __shared__ float  s_warp[THREADS / 32];
    __shared__ float4 s_part[16];              // published CTA-partial sum (peer reads this)
    __shared__ float  s_pssq;                  // published CTA-partial sum of sq-norms
    __shared__ float4 s_mean[16];              // combined -> mean
    __shared__ float  s_totssq;
    __shared__ float  s_inv;
    __shared__ int    s_lo, s_hi;

    const int tid = threadIdx.x;
    const int seg  = (int)(blockIdx.x >> 1);
    const uint32_t rank = blockIdx.x & 1u;
    const uint32_t peer = rank ^ 1u;

    if (tid == 0)  s_lo = lower_bound_i32(batch, N, seg);
    if (tid == 32) s_hi = lower_bound_i32(batch, N, seg + 1);
    __syncthreads();
    const int lo = s_lo, hi = s_hi;
    const int cnt = hi - lo;
    const int h0 = (cnt + 1) >> 1;
    const int mylo = rank ? (lo + h0) : lo;
    const int myhi = rank ? hi        : (lo + h0);

    const int lane16 = tid & 15;
    const int rg     = tid >> 4;

    // ---- Pass 1: this CTA's half-segment: sum[64] + sum of squared norms ----
    float4 acc = make_float4(0.f, 0.f, 0.f, 0.f);
    float ssq = 0.f;
    #pragma unroll 8
    for (int r = mylo + rg; r < myhi; r += ROWG) {
        float4 v = x4[(size_t)r * 16 + lane16];
        acc.x += v.x; acc.y += v.y; acc.z += v.z; acc.w += v.w;
        ssq += v.x * v.x + v.y * v.y + v.z * v.z + v.w * v.w;
    }
    s_red[rg * 16 + lane16] = acc;

    #pragma unroll
    for (int off = 16; off > 0; off >>= 1)
        ssq += __shfl_xor_sync(0xffffffffu, ssq, off);
    if ((tid & 31) == 0) s_warp[tid >> 5] = ssq;
    __syncthreads();

    #pragma unroll
    for (int off = ROWG / 2; off >= 1; off >>= 1) {
        if (rg < off) {
            float4 a = s_red[rg * 16 + lane16];
            float4 b = s_red[(rg + off) * 16 + lane16];
            a.x += b.x; a.y += b.y; a.z += b.z; a.w += b.w;
            s_red[rg * 16 + lane16] = a;
        }
        __syncthreads();
    }

    // publish CTA-local partials for the peer
    if (tid < 16) s_part[tid] = s_red[tid];
    if (tid == 16) {
        float t = 0.f;
        #pragma unroll
        for (int w = 0; w < THREADS / 32; w++) t += s_warp[w];
        s_pssq = t;
    }
    __syncthreads();

    // cluster barrier: peer's partials are now written & visible
    CLUSTER_SYNC();

    // combine local + peer partials
    if (tid < 64) {
        float mine   = ((const float*)s_part)[tid];
        float theirs = ld_peer_f32(smem_u32(s_part) + (uint32_t)tid * 4u, peer);
        ((float*)s_mean)[tid] = mine + theirs;
    } else if (tid == 64) {
        float theirs = ld_peer_f32(smem_u32(&s_pssq), peer);
        s_totssq = s_pssq + theirs;
    }
    __syncthreads();

    // finalize: mean and 1/sqrt(mean centered sq-norm)
    if (tid == 0) {
        const float invc = 1.f / (float)(cnt > 0 ? cnt : 1);
        float msq = 0.f;
        #pragma unroll
        for (int i = 0; i < 16; i++) {
            float4 m = s_mean[i];
            m.x *= invc; m.y *= invc; m.z *= invc; m.w *= invc;
            s_mean[i] = m;
            msq += m.x * m.x + m.y * m.y + m.z * m.z + m.w * m.w;
        }
        // sum||x-m||^2 / cnt = sumsq/cnt - ||m||^2
        float var = fmaxf(s_totssq * invc - msq, 0.f);
        s_inv = rsqrtf(var);
    }
    __syncthreads();

    const float4 mean = s_mean[lane16];
    const float inv = s_inv;

    // ---- Pass 2: re-read own half (L2-resident) and write normalized output ----
    #pragma unroll 8
    for (int r = mylo + rg; r < myhi; r += ROWG) {
        float4 v = x4[(size_t)r * 16 + lane16];
        float4 o;
        o.x = (v.x - mean.x) * inv;
        o.y = (v.y - mean.y) * inv;
        o.z = (v.z - mean.z) * inv;
        o.w = (v.w - mean.w) * inv;
        out4[(size_t)r * 16 + lane16] = o;
    }

    // keep DSMEM valid until both CTAs are done touching peer smem
    CLUSTER_SYNC();
}

extern "C" void kernel_launch(void* const* d_in, const int* in_sizes, int n_in,
                              void* d_out, int out_size)
{
    const float4* x4    = (const float4*)d_in[0];
    const int*    batch = (const int*)d_in[1];
    float4*       out4  = (float4*)d_out;
    const int N = in_sizes[1];   // 1,000,000 rows; D = 64 fixed

    // 96 KB dynamic smem: 3 CTAs would exceed the 227 KB/SM cap -> exactly
    // 2 CTAs/SM. Concurrent clusters = 148 -> 148 segments x ~500 KB = 74 MB
    // resident in L2 for the pass-2 re-read.
    static const int kSmem = 96 * 1024;
    cudaFuncSetAttribute(pairnorm_kernel, cudaFuncAttributeMaxDynamicSharedMemorySize, kSmem);
    pairnorm_kernel<<<2 * NUM_SEGMENTS, THREADS, kSmem>>>(x4, batch, out4, N);
}